// round 1
// baseline (speedup 1.0000x reference)
#include <cuda_runtime.h>
#include <math.h>

#define N_NODES 50000
#define N_EDGES 800000
#define D 128
#define DIN 8

// ---------------- scratch (static __device__, no allocations) ----------------
__device__ float g_deg[N_NODES];
__device__ float g_dinv[N_NODES];
__device__ float g_h[N_NODES * D];     // layer feature buffer (h1 path)
__device__ float g_agg[N_NODES * D];   // scatter-add accumulator
__device__ float g_h2[N_NODES * D];    // layer-2 features

// ---------------- kernels ----------------

// zero deg + agg (agg may be dirty from previous launch's layer-2 agg)
__global__ void k_zero(void) {
    int idx = blockIdx.x * blockDim.x + threadIdx.x;
    if (idx < N_NODES * D) g_agg[idx] = 0.0f;
    if (idx < N_NODES)     g_deg[idx] = 0.0f;
}

__global__ void k_deg(const int* __restrict__ dst) {
    int e = blockIdx.x * blockDim.x + threadIdx.x;
    if (e < N_EDGES) atomicAdd(&g_deg[dst[e]], 1.0f);
}

__global__ void k_dinv(void) {
    int i = blockIdx.x * blockDim.x + threadIdx.x;
    if (i < N_NODES) g_dinv[i] = rsqrtf(g_deg[i] + 1.0f);
}

// h = x @ W1   (no bias here; bias folded into self-loop kernel)
__global__ void k_mm1(const float* __restrict__ x, const float* __restrict__ W1) {
    int idx = blockIdx.x * blockDim.x + threadIdx.x;
    if (idx >= N_NODES * D) return;
    int node = idx >> 7;
    int j = idx & 127;
    float acc = 0.0f;
#pragma unroll
    for (int k = 0; k < DIN; k++)
        acc = fmaf(x[node * DIN + k], W1[k * D + j], acc);
    g_h[idx] = acc;
}

// agg[dst] += hin[src] * dinv[src]*dinv[dst]   (warp per edge, 4 feats/lane)
__global__ void k_agg(const float* __restrict__ hin,
                      const int* __restrict__ src, const int* __restrict__ dst) {
    int gw = (blockIdx.x * blockDim.x + threadIdx.x) >> 5;
    int lane = threadIdx.x & 31;
    int nw = (gridDim.x * blockDim.x) >> 5;
    for (int e = gw; e < N_EDGES; e += nw) {
        int s = src[e];
        int d2 = dst[e];
        float nrm = g_dinv[s] * g_dinv[d2];
        float4 v = __ldcs(reinterpret_cast<const float4*>(hin + s * D) + lane);
        float* base = g_agg + d2 * D + 4 * lane;
        atomicAdd(base + 0, v.x * nrm);
        atomicAdd(base + 1, v.y * nrm);
        atomicAdd(base + 2, v.z * nrm);
        atomicAdd(base + 3, v.w * nrm);
    }
}

// hio = relu(agg + hio*dinv^2 + b); optionally re-zero agg for next layer
__global__ void k_self(const float* __restrict__ b, float* __restrict__ hio,
                       int zero_agg) {
    int idx = blockIdx.x * blockDim.x + threadIdx.x;
    if (idx >= N_NODES * D) return;
    int node = idx >> 7;
    int j = idx & 127;
    float di = g_dinv[node];
    float v = g_agg[idx] + hio[idx] * di * di + b[j];
    hio[idx] = fmaxf(v, 0.0f);
    if (zero_agg) g_agg[idx] = 0.0f;  // each element touched exactly once -> safe
}

// g_h2 = g_h @ W2   (block per node, 128 threads)
__global__ void k_mm2(const float* __restrict__ W2) {
    __shared__ float row[D];
    int node = blockIdx.x;
    int j = threadIdx.x;
    row[j] = g_h[node * D + j];
    __syncthreads();
    float acc = 0.0f;
#pragma unroll 8
    for (int k = 0; k < D; k++)
        acc = fmaf(row[k], W2[k * D + j], acc);
    g_h2[node * D + j] = acc;
}

// Edge MLP: out[e] = log_softmax( relu(concat(h2[src],h2[dst]) @ Wl + bl) @ Wf + bf )
// 8 warps/block, each warp processes 4 edges at a time; each lane owns 4 hidden
// units (j = 4*lane..4*lane+3) for all 4 edges; W float4 register-cached across
// the 4 edges (16 FMA per W load).
__global__ void __launch_bounds__(256) k_edge_mlp(
    const int* __restrict__ src, const int* __restrict__ dst,
    const float* __restrict__ Wl, const float* __restrict__ bl,
    const float* __restrict__ Wf, const float* __restrict__ bf,
    float* __restrict__ out) {
    __shared__ __align__(16) float xp[8][4][2 * D];
    int warp = threadIdx.x >> 5;
    int lane = threadIdx.x & 31;
    int gw = blockIdx.x * 8 + warp;
    int nw = gridDim.x * 8;

    float bf0 = bf[0], bf1 = bf[1];
    float wf0[4], wf1[4], bl4[4];
#pragma unroll
    for (int i = 0; i < 4; i++) {
        wf0[i] = Wf[(4 * lane + i) * 2 + 0];
        wf1[i] = Wf[(4 * lane + i) * 2 + 1];
        bl4[i] = bl[4 * lane + i];
    }

    const float4* Wl4 = reinterpret_cast<const float4*>(Wl);

    for (int e0 = gw * 4; e0 < N_EDGES; e0 += nw * 4) {
        // gather concat(h2[src], h2[dst]) for 4 edges into smem (streaming loads)
#pragma unroll
        for (int ee = 0; ee < 4; ee++) {
            int e = e0 + ee;  // N_EDGES divisible by 4
            int s = src[e];
            int d2 = dst[e];
            float4 vs = __ldcs(reinterpret_cast<const float4*>(g_h2 + s * D) + lane);
            float4 vd = __ldcs(reinterpret_cast<const float4*>(g_h2 + d2 * D) + lane);
            *reinterpret_cast<float4*>(&xp[warp][ee][4 * lane]) = vs;
            *reinterpret_cast<float4*>(&xp[warp][ee][D + 4 * lane]) = vd;
        }
        __syncwarp();

        float acc[4][4];
#pragma unroll
        for (int ee = 0; ee < 4; ee++)
#pragma unroll
            for (int i = 0; i < 4; i++) acc[ee][i] = bl4[i];

#pragma unroll 4
        for (int k = 0; k < 2 * D; k++) {
            float4 w = __ldg(Wl4 + k * (D / 4) + lane);
#pragma unroll
            for (int ee = 0; ee < 4; ee++) {
                float xk = xp[warp][ee][k];
                acc[ee][0] = fmaf(xk, w.x, acc[ee][0]);
                acc[ee][1] = fmaf(xk, w.y, acc[ee][1]);
                acc[ee][2] = fmaf(xk, w.z, acc[ee][2]);
                acc[ee][3] = fmaf(xk, w.w, acc[ee][3]);
            }
        }

        // epilogue: relu -> 2 logits (warp reduce) -> log_softmax
#pragma unroll
        for (int ee = 0; ee < 4; ee++) {
            float z0 = 0.0f, z1 = 0.0f;
#pragma unroll
            for (int i = 0; i < 4; i++) {
                float h = fmaxf(acc[ee][i], 0.0f);
                z0 = fmaf(h, wf0[i], z0);
                z1 = fmaf(h, wf1[i], z1);
            }
#pragma unroll
            for (int off = 16; off; off >>= 1) {
                z0 += __shfl_xor_sync(0xffffffffu, z0, off);
                z1 += __shfl_xor_sync(0xffffffffu, z1, off);
            }
            if (lane == 0) {
                z0 += bf0;
                z1 += bf1;
                float m = fmaxf(z0, z1);
                float lse = m + logf(expf(z0 - m) + expf(z1 - m));
                float2 o;
                o.x = z0 - lse;
                o.y = z1 - lse;
                *reinterpret_cast<float2*>(out + (size_t)(e0 + ee) * 2) = o;
            }
        }
        __syncwarp();
    }
}

// ---------------- launch ----------------
extern "C" void kernel_launch(void* const* d_in, const int* in_sizes, int n_in,
                              void* d_out, int out_size) {
    const float* x     = (const float*)d_in[0];
    const int*   eidx  = (const int*)d_in[1];
    const float* W1    = (const float*)d_in[2];
    const float* b1    = (const float*)d_in[3];
    const float* W2    = (const float*)d_in[4];
    const float* b2    = (const float*)d_in[5];
    const float* Wlin1 = (const float*)d_in[6];
    const float* blin1 = (const float*)d_in[7];
    const float* Wfin  = (const float*)d_in[8];
    const float* bfin  = (const float*)d_in[9];
    float* out = (float*)d_out;

    const int* src = eidx;
    const int* dst = eidx + N_EDGES;

    const int ND = N_NODES * D;

    // layer 1
    k_zero<<<(ND + 255) / 256, 256>>>();
    k_deg<<<(N_EDGES + 255) / 256, 256>>>(dst);
    k_dinv<<<(N_NODES + 255) / 256, 256>>>();
    k_mm1<<<(ND + 255) / 256, 256>>>(x, W1);

    // get device addresses of the __device__ arrays via a tiny trampoline:
    // (pointers to __device__ globals are usable directly in device code; for
    //  host-side argument passing we use cudaGetSymbolAddress — not a stream op,
    //  safe under graph capture)
    static float* p_h = nullptr;
    static float* p_h2 = nullptr;
    if (!p_h)  cudaGetSymbolAddress((void**)&p_h,  g_h);
    if (!p_h2) cudaGetSymbolAddress((void**)&p_h2, g_h2);

    k_agg<<<2368, 256>>>(p_h, src, dst);
    k_self<<<(ND + 255) / 256, 256>>>(b1, p_h, /*zero_agg=*/1);

    // layer 2
    k_mm2<<<N_NODES, D>>>(W2);
    k_agg<<<2368, 256>>>(p_h2, src, dst);
    k_self<<<(ND + 255) / 256, 256>>>(b2, p_h2, /*zero_agg=*/0);

    // edge MLP + classifier
    k_edge_mlp<<<2368, 256>>>(src, dst, Wlin1, blin1, Wfin, bfin, out);
}

// round 2
// speedup vs baseline: 2.9514x; 2.9514x over previous
#include <cuda_runtime.h>
#include <math.h>

#define N_NODES 50000
#define N_EDGES 800000
#define D 128

// ---------------- scratch (__device__ globals; no allocations) ----------------
__device__ int   g_deg[N_NODES];
__device__ int   g_ptr[N_NODES + 1];
__device__ int   g_cnt[N_NODES];
__device__ int   g_es[N_EDGES];          // src id per dst-sorted slot
__device__ float g_dinv[N_NODES];
__device__ float g_h[N_NODES * D];       // ping
__device__ float g_hb[N_NODES * D];      // pong
__device__ float g_h2[N_NODES * D];      // layer-2 output features
__device__ float g_ab[N_NODES * 2 * D];  // [A | B] per node (edge-MLP factorization)

// ---------------- CSR build ----------------
__global__ void k_zero_deg(void) {
    int i = blockIdx.x * blockDim.x + threadIdx.x;
    if (i < N_NODES) g_deg[i] = 0;
}

__global__ void k_deg(const int* __restrict__ dst) {
    int e = blockIdx.x * blockDim.x + threadIdx.x;
    if (e < N_EDGES) atomicAdd(&g_deg[dst[e]], 1);
}

// single-block exclusive scan over 50000 degrees; also dinv + cnt init
__global__ void k_scan(void) {
    __shared__ int part[1024];
    int t = threadIdx.x;
    const int CH = (N_NODES + 1023) / 1024;  // 49
    int begin = t * CH;
    int end = begin + CH; if (end > N_NODES) end = N_NODES;
    int s = 0;
    for (int i = begin; i < end; i++) s += g_deg[i];
    part[t] = s;
    __syncthreads();
    for (int off = 1; off < 1024; off <<= 1) {
        int v = (t >= off) ? part[t - off] : 0;
        __syncthreads();
        part[t] += v;
        __syncthreads();
    }
    int run = (t == 0) ? 0 : part[t - 1];
    for (int i = begin; i < end; i++) {
        int d = g_deg[i];
        g_ptr[i] = run;
        g_cnt[i] = run;
        g_dinv[i] = rsqrtf((float)d + 1.0f);
        run += d;
    }
    if (t == 1023) g_ptr[N_NODES] = run;
}

__global__ void k_scatter(const int* __restrict__ src, const int* __restrict__ dst) {
    int e = blockIdx.x * blockDim.x + threadIdx.x;
    if (e < N_EDGES) {
        int d = dst[e];
        int pos = atomicAdd(&g_cnt[d], 1);
        g_es[pos] = src[e];
    }
}

// ---------------- h = x @ W1 (D_IN=8) ----------------
__global__ void k_mm1(const float* __restrict__ x, const float* __restrict__ W1) {
    int idx = blockIdx.x * blockDim.x + threadIdx.x;
    if (idx >= N_NODES * D) return;
    int node = idx >> 7;
    int j = idx & 127;
    float acc = 0.0f;
#pragma unroll
    for (int k = 0; k < 8; k++)
        acc = fmaf(x[node * 8 + k], W1[k * D + j], acc);
    g_h[idx] = acc;
}

// ---------------- fused GCN aggregation (CSR, warp/node) + self + bias + relu ----------------
__global__ void __launch_bounds__(256) k_gcn(const float* __restrict__ hin,
                                             float* __restrict__ hout,
                                             const float* __restrict__ b) {
    int warp = threadIdx.x >> 5;
    int lane = threadIdx.x & 31;
    int node = blockIdx.x * 8 + warp;
    if (node >= N_NODES) return;

    int p0 = g_ptr[node], p1 = g_ptr[node + 1];
    float4 acc = make_float4(0.f, 0.f, 0.f, 0.f);
    for (int i = p0; i < p1; i++) {
        int s = g_es[i];
        float w = g_dinv[s];
        float4 v = __ldcs(reinterpret_cast<const float4*>(hin + (size_t)s * D) + lane);
        acc.x = fmaf(v.x, w, acc.x);
        acc.y = fmaf(v.y, w, acc.y);
        acc.z = fmaf(v.z, w, acc.z);
        acc.w = fmaf(v.w, w, acc.w);
    }
    float di = g_dinv[node];
    float di2 = di * di;
    float4 self = *(reinterpret_cast<const float4*>(hin + (size_t)node * D) + lane);
    float4 bb = *(reinterpret_cast<const float4*>(b) + lane);
    float4 r;
    r.x = fmaxf(fmaf(acc.x, di, fmaf(self.x, di2, bb.x)), 0.f);
    r.y = fmaxf(fmaf(acc.y, di, fmaf(self.y, di2, bb.y)), 0.f);
    r.z = fmaxf(fmaf(acc.z, di, fmaf(self.z, di2, bb.z)), 0.f);
    r.w = fmaxf(fmaf(acc.w, di, fmaf(self.w, di2, bb.w)), 0.f);
    *(reinterpret_cast<float4*>(hout + (size_t)node * D) + lane) = r;
}

// ---------------- out = in @ W (128x128), 8 nodes per block ----------------
__global__ void __launch_bounds__(128) k_mm128(const float* __restrict__ in,
                                               const float* __restrict__ W,
                                               float* __restrict__ out) {
    __shared__ float sm[8][D];
    int j = threadIdx.x;
    int base = blockIdx.x * 8;
#pragma unroll
    for (int nn = 0; nn < 8; nn++) sm[nn][j] = in[(size_t)(base + nn) * D + j];
    __syncthreads();
    float acc[8] = {0.f, 0.f, 0.f, 0.f, 0.f, 0.f, 0.f, 0.f};
#pragma unroll 4
    for (int k = 0; k < D; k++) {
        float w = __ldg(W + k * D + j);
#pragma unroll
        for (int nn = 0; nn < 8; nn++) acc[nn] = fmaf(sm[nn][k], w, acc[nn]);
    }
#pragma unroll
    for (int nn = 0; nn < 8; nn++) out[(size_t)(base + nn) * D + j] = acc[nn];
}

// ---------------- g_ab[n] = [ h2[n]@Wl_top | h2[n]@Wl_bot ], 8 nodes/block ----------------
__global__ void __launch_bounds__(128) k_ab(const float* __restrict__ h2,
                                            const float* __restrict__ Wl) {
    __shared__ float sm[8][D];
    int j = threadIdx.x;
    int base = blockIdx.x * 8;
#pragma unroll
    for (int nn = 0; nn < 8; nn++) sm[nn][j] = h2[(size_t)(base + nn) * D + j];
    __syncthreads();
    float accA[8] = {0.f, 0.f, 0.f, 0.f, 0.f, 0.f, 0.f, 0.f};
    float accB[8] = {0.f, 0.f, 0.f, 0.f, 0.f, 0.f, 0.f, 0.f};
#pragma unroll 4
    for (int k = 0; k < D; k++) {
        float wA = __ldg(Wl + k * D + j);
        float wB = __ldg(Wl + (D + k) * D + j);
#pragma unroll
        for (int nn = 0; nn < 8; nn++) {
            float xk = sm[nn][k];
            accA[nn] = fmaf(xk, wA, accA[nn]);
            accB[nn] = fmaf(xk, wB, accB[nn]);
        }
    }
#pragma unroll
    for (int nn = 0; nn < 8; nn++) {
        out_store:
        g_ab[(size_t)(base + nn) * 2 * D + j] = accA[nn];
        g_ab[(size_t)(base + nn) * 2 * D + D + j] = accB[nn];
    }
}

// ---------------- edge kernel: hidden = relu(A[s]+B[d]+bl); logits; log_softmax ----------------
__global__ void __launch_bounds__(256) k_edge(const int* __restrict__ src,
                                              const int* __restrict__ dst,
                                              const float* __restrict__ bl,
                                              const float* __restrict__ Wf,
                                              const float* __restrict__ bf,
                                              float* __restrict__ out) {
    int lane = threadIdx.x & 31;
    int gw = (blockIdx.x * blockDim.x + threadIdx.x) >> 5;
    int nw = (gridDim.x * blockDim.x) >> 5;

    float bf0 = bf[0], bf1 = bf[1];
    float wf0[4], wf1[4];
    float4 bl4 = *(reinterpret_cast<const float4*>(bl) + lane);
#pragma unroll
    for (int i = 0; i < 4; i++) {
        wf0[i] = Wf[(4 * lane + i) * 2 + 0];
        wf1[i] = Wf[(4 * lane + i) * 2 + 1];
    }

    for (int e0 = gw * 2; e0 < N_EDGES; e0 += nw * 2) {
        int s0 = src[e0], d0 = dst[e0];
        int s1 = src[e0 + 1], d1 = dst[e0 + 1];
        float4 a0 = __ldcs(reinterpret_cast<const float4*>(g_ab + (size_t)s0 * 2 * D) + lane);
        float4 c0 = __ldcs(reinterpret_cast<const float4*>(g_ab + (size_t)d0 * 2 * D + D) + lane);
        float4 a1 = __ldcs(reinterpret_cast<const float4*>(g_ab + (size_t)s1 * 2 * D) + lane);
        float4 c1 = __ldcs(reinterpret_cast<const float4*>(g_ab + (size_t)d1 * 2 * D + D) + lane);

        float h0[4], h1v[4];
        h0[0] = fmaxf(a0.x + c0.x + bl4.x, 0.f);
        h0[1] = fmaxf(a0.y + c0.y + bl4.y, 0.f);
        h0[2] = fmaxf(a0.z + c0.z + bl4.z, 0.f);
        h0[3] = fmaxf(a0.w + c0.w + bl4.w, 0.f);
        h1v[0] = fmaxf(a1.x + c1.x + bl4.x, 0.f);
        h1v[1] = fmaxf(a1.y + c1.y + bl4.y, 0.f);
        h1v[2] = fmaxf(a1.z + c1.z + bl4.z, 0.f);
        h1v[3] = fmaxf(a1.w + c1.w + bl4.w, 0.f);

        float z00 = 0.f, z01 = 0.f, z10 = 0.f, z11 = 0.f;
#pragma unroll
        for (int i = 0; i < 4; i++) {
            z00 = fmaf(h0[i], wf0[i], z00);
            z01 = fmaf(h0[i], wf1[i], z01);
            z10 = fmaf(h1v[i], wf0[i], z10);
            z11 = fmaf(h1v[i], wf1[i], z11);
        }
#pragma unroll
        for (int off = 16; off; off >>= 1) {
            z00 += __shfl_xor_sync(0xffffffffu, z00, off);
            z01 += __shfl_xor_sync(0xffffffffu, z01, off);
            z10 += __shfl_xor_sync(0xffffffffu, z10, off);
            z11 += __shfl_xor_sync(0xffffffffu, z11, off);
        }
        if (lane == 0) {
            float x0 = z00 + bf0, x1 = z01 + bf1;
            float m = fmaxf(x0, x1);
            float lse = m + logf(expf(x0 - m) + expf(x1 - m));
            float2 o0 = make_float2(x0 - lse, x1 - lse);
            *reinterpret_cast<float2*>(out + (size_t)e0 * 2) = o0;

            float y0 = z10 + bf0, y1 = z11 + bf1;
            float m2 = fmaxf(y0, y1);
            float lse2 = m2 + logf(expf(y0 - m2) + expf(y1 - m2));
            float2 o1 = make_float2(y0 - lse2, y1 - lse2);
            *reinterpret_cast<float2*>(out + (size_t)(e0 + 1) * 2) = o1;
        }
    }
}

// ---------------- launch ----------------
extern "C" void kernel_launch(void* const* d_in, const int* in_sizes, int n_in,
                              void* d_out, int out_size) {
    const float* x     = (const float*)d_in[0];
    const int*   eidx  = (const int*)d_in[1];
    const float* W1    = (const float*)d_in[2];
    const float* b1    = (const float*)d_in[3];
    const float* W2    = (const float*)d_in[4];
    const float* b2    = (const float*)d_in[5];
    const float* Wlin1 = (const float*)d_in[6];
    const float* blin1 = (const float*)d_in[7];
    const float* Wfin  = (const float*)d_in[8];
    const float* bfin  = (const float*)d_in[9];
    float* out = (float*)d_out;

    const int* src = eidx;
    const int* dst = eidx + N_EDGES;

    static float *p_h = nullptr, *p_hb = nullptr, *p_h2 = nullptr;
    if (!p_h)  cudaGetSymbolAddress((void**)&p_h,  g_h);
    if (!p_hb) cudaGetSymbolAddress((void**)&p_hb, g_hb);
    if (!p_h2) cudaGetSymbolAddress((void**)&p_h2, g_h2);

    const int ND = N_NODES * D;
    const int EB = (N_EDGES + 255) / 256;

    // CSR build (shared by both GCN layers)
    k_zero_deg<<<(N_NODES + 255) / 256, 256>>>();
    k_deg<<<EB, 256>>>(dst);
    k_scan<<<1, 1024>>>();
    k_scatter<<<EB, 256>>>(src, dst);

    // layer 1: h = relu(GCN(x@W1))
    k_mm1<<<(ND + 255) / 256, 256>>>(x, W1);
    k_gcn<<<(N_NODES + 7) / 8, 256>>>(p_h, p_hb, b1);

    // layer 2: h2 = relu(GCN(hb@W2))
    k_mm128<<<N_NODES / 8, 128>>>(p_hb, W2, p_h);
    k_gcn<<<(N_NODES + 7) / 8, 256>>>(p_h, p_h2, b2);

    // edge MLP factorization: A|B = h2 @ [Wl_top | Wl_bot]
    k_ab<<<N_NODES / 8, 128>>>(p_h2, Wlin1);

    // per-edge: relu(A[s]+B[d]+bl) -> 2 logits -> log_softmax
    k_edge<<<2368, 256>>>(src, dst, blin1, Wfin, bfin, out);
}

// round 3
// speedup vs baseline: 4.5786x; 1.5513x over previous
#include <cuda_runtime.h>
#include <math.h>

#define N_NODES 50000
#define N_PAD   50048            // multiple of 32 for GEMM tiling; pad rows stay 0
#define N_EDGES 800000
#define D 128

// ---------------- scratch (__device__ globals; no allocations) ----------------
__device__ int   g_deg[N_NODES];
__device__ int   g_ptr[N_NODES + 1];
__device__ int   g_cnt[N_NODES];
__device__ int   g_es[N_EDGES];            // src id per dst-sorted slot
__device__ float g_dinv[N_NODES];
__device__ float g_h[N_PAD * D];           // ping
__device__ float g_hb[N_PAD * D];          // pong
__device__ float g_h2[N_PAD * D];          // layer-2 output features
__device__ float g_ab[N_PAD * 2 * D];      // [A | B] per node

// ---------------- CSR build ----------------
__global__ void k_zero_deg(void) {
    int i = blockIdx.x * blockDim.x + threadIdx.x;
    if (i < N_NODES) g_deg[i] = 0;
}

__global__ void k_deg(const int* __restrict__ dst) {
    int e = blockIdx.x * blockDim.x + threadIdx.x;
    if (e < N_EDGES) atomicAdd(&g_deg[dst[e]], 1);
}

// single-block exclusive scan over degrees; also dinv + cnt init
__global__ void k_scan(void) {
    __shared__ int part[1024];
    int t = threadIdx.x;
    const int CH = (N_NODES + 1023) / 1024;
    int begin = t * CH;
    int end = begin + CH; if (end > N_NODES) end = N_NODES;
    int s = 0;
    for (int i = begin; i < end; i++) s += g_deg[i];
    part[t] = s;
    __syncthreads();
    for (int off = 1; off < 1024; off <<= 1) {
        int v = (t >= off) ? part[t - off] : 0;
        __syncthreads();
        part[t] += v;
        __syncthreads();
    }
    int run = (t == 0) ? 0 : part[t - 1];
    for (int i = begin; i < end; i++) {
        int d = g_deg[i];
        g_ptr[i] = run;
        g_cnt[i] = run;
        g_dinv[i] = rsqrtf((float)d + 1.0f);
        run += d;
    }
    if (t == 1023) g_ptr[N_NODES] = run;
}

__global__ void k_scatter(const int* __restrict__ src, const int* __restrict__ dst) {
    int e = blockIdx.x * blockDim.x + threadIdx.x;
    if (e < N_EDGES) {
        int d = dst[e];
        int pos = atomicAdd(&g_cnt[d], 1);
        g_es[pos] = src[e];
    }
}

// ---------------- h = x @ W1 (D_IN=8) ----------------
__global__ void k_mm1(const float* __restrict__ x, const float* __restrict__ W1) {
    int idx = blockIdx.x * blockDim.x + threadIdx.x;
    if (idx >= N_NODES * D) return;
    int node = idx >> 7;
    int j = idx & 127;
    float acc = 0.0f;
#pragma unroll
    for (int k = 0; k < 8; k++)
        acc = fmaf(x[node * 8 + k], W1[k * D + j], acc);
    g_h[idx] = acc;
}

// ---------------- fused GCN agg (CSR, warp/node, x4 unrolled) + self + bias + relu ----------------
__global__ void __launch_bounds__(256) k_gcn(const float* __restrict__ hin,
                                             float* __restrict__ hout,
                                             const float* __restrict__ b) {
    int warp = threadIdx.x >> 5;
    int lane = threadIdx.x & 31;
    int node = blockIdx.x * 8 + warp;
    if (node >= N_NODES) return;

    int p0 = g_ptr[node], p1 = g_ptr[node + 1];
    float4 acc = make_float4(0.f, 0.f, 0.f, 0.f);
    int i = p0;
    for (; i + 4 <= p1; i += 4) {
        int s0 = g_es[i], s1 = g_es[i + 1], s2 = g_es[i + 2], s3 = g_es[i + 3];
        float w0 = g_dinv[s0], w1 = g_dinv[s1], w2 = g_dinv[s2], w3 = g_dinv[s3];
        float4 v0 = __ldg(reinterpret_cast<const float4*>(hin + (size_t)s0 * D) + lane);
        float4 v1 = __ldg(reinterpret_cast<const float4*>(hin + (size_t)s1 * D) + lane);
        float4 v2 = __ldg(reinterpret_cast<const float4*>(hin + (size_t)s2 * D) + lane);
        float4 v3 = __ldg(reinterpret_cast<const float4*>(hin + (size_t)s3 * D) + lane);
        acc.x = fmaf(v0.x, w0, fmaf(v1.x, w1, fmaf(v2.x, w2, fmaf(v3.x, w3, acc.x))));
        acc.y = fmaf(v0.y, w0, fmaf(v1.y, w1, fmaf(v2.y, w2, fmaf(v3.y, w3, acc.y))));
        acc.z = fmaf(v0.z, w0, fmaf(v1.z, w1, fmaf(v2.z, w2, fmaf(v3.z, w3, acc.z))));
        acc.w = fmaf(v0.w, w0, fmaf(v1.w, w1, fmaf(v2.w, w2, fmaf(v3.w, w3, acc.w))));
    }
    for (; i < p1; i++) {
        int s = g_es[i];
        float w = g_dinv[s];
        float4 v = __ldg(reinterpret_cast<const float4*>(hin + (size_t)s * D) + lane);
        acc.x = fmaf(v.x, w, acc.x);
        acc.y = fmaf(v.y, w, acc.y);
        acc.z = fmaf(v.z, w, acc.z);
        acc.w = fmaf(v.w, w, acc.w);
    }
    float di = g_dinv[node];
    float di2 = di * di;
    float4 self = *(reinterpret_cast<const float4*>(hin + (size_t)node * D) + lane);
    float4 bb = *(reinterpret_cast<const float4*>(b) + lane);
    float4 r;
    r.x = fmaxf(fmaf(acc.x, di, fmaf(self.x, di2, bb.x)), 0.f);
    r.y = fmaxf(fmaf(acc.y, di, fmaf(self.y, di2, bb.y)), 0.f);
    r.z = fmaxf(fmaf(acc.z, di, fmaf(self.z, di2, bb.z)), 0.f);
    r.w = fmaxf(fmaf(acc.w, di, fmaf(self.w, di2, bb.w)), 0.f);
    *(reinterpret_cast<float4*>(hout + (size_t)node * D) + lane) = r;
}

// ---------------- out = in @ W (128x128): 32-node tile, 256 thr, 4x4 blocking ----------------
__global__ void __launch_bounds__(256) k_mm128(const float* __restrict__ in,
                                               const float* __restrict__ W,
                                               float* __restrict__ out) {
    __shared__ float sx[32][D];
    int base = blockIdx.x * 32;
    const float4* in4 = reinterpret_cast<const float4*>(in + (size_t)base * D);
    float4* sx4 = reinterpret_cast<float4*>(&sx[0][0]);
#pragma unroll
    for (int i = threadIdx.x; i < 32 * D / 4; i += 256) sx4[i] = in4[i];
    __syncthreads();

    int cg = threadIdx.x & 31;   // 4-col group
    int ng = threadIdx.x >> 5;   // 4-node group
    float acc[4][4] = {};
#pragma unroll 4
    for (int k = 0; k < D; k++) {
        float4 w = __ldg(reinterpret_cast<const float4*>(W + k * D) + cg);
        float x0 = sx[4 * ng + 0][k];
        float x1 = sx[4 * ng + 1][k];
        float x2 = sx[4 * ng + 2][k];
        float x3 = sx[4 * ng + 3][k];
        acc[0][0] = fmaf(x0, w.x, acc[0][0]); acc[0][1] = fmaf(x0, w.y, acc[0][1]);
        acc[0][2] = fmaf(x0, w.z, acc[0][2]); acc[0][3] = fmaf(x0, w.w, acc[0][3]);
        acc[1][0] = fmaf(x1, w.x, acc[1][0]); acc[1][1] = fmaf(x1, w.y, acc[1][1]);
        acc[1][2] = fmaf(x1, w.z, acc[1][2]); acc[1][3] = fmaf(x1, w.w, acc[1][3]);
        acc[2][0] = fmaf(x2, w.x, acc[2][0]); acc[2][1] = fmaf(x2, w.y, acc[2][1]);
        acc[2][2] = fmaf(x2, w.z, acc[2][2]); acc[2][3] = fmaf(x2, w.w, acc[2][3]);
        acc[3][0] = fmaf(x3, w.x, acc[3][0]); acc[3][1] = fmaf(x3, w.y, acc[3][1]);
        acc[3][2] = fmaf(x3, w.z, acc[3][2]); acc[3][3] = fmaf(x3, w.w, acc[3][3]);
    }
#pragma unroll
    for (int nn = 0; nn < 4; nn++) {
        float4 v = make_float4(acc[nn][0], acc[nn][1], acc[nn][2], acc[nn][3]);
        *(reinterpret_cast<float4*>(out + (size_t)(base + 4 * ng + nn) * D) + cg) = v;
    }
}

// ---------------- g_ab = h2 @ [Wl_top | Wl_bot]: 32-node tile, 4x(4A+4B) blocking ----------------
__global__ void __launch_bounds__(256) k_ab(const float* __restrict__ h2,
                                            const float* __restrict__ Wl) {
    __shared__ float sx[32][D];
    int base = blockIdx.x * 32;
    const float4* in4 = reinterpret_cast<const float4*>(h2 + (size_t)base * D);
    float4* sx4 = reinterpret_cast<float4*>(&sx[0][0]);
#pragma unroll
    for (int i = threadIdx.x; i < 32 * D / 4; i += 256) sx4[i] = in4[i];
    __syncthreads();

    int cg = threadIdx.x & 31;
    int ng = threadIdx.x >> 5;
    float accA[4][4] = {};
    float accB[4][4] = {};
#pragma unroll 2
    for (int k = 0; k < D; k++) {
        float4 wA = __ldg(reinterpret_cast<const float4*>(Wl + k * D) + cg);
        float4 wB = __ldg(reinterpret_cast<const float4*>(Wl + (D + k) * D) + cg);
        float x0 = sx[4 * ng + 0][k];
        float x1 = sx[4 * ng + 1][k];
        float x2 = sx[4 * ng + 2][k];
        float x3 = sx[4 * ng + 3][k];
        accA[0][0] = fmaf(x0, wA.x, accA[0][0]); accA[0][1] = fmaf(x0, wA.y, accA[0][1]);
        accA[0][2] = fmaf(x0, wA.z, accA[0][2]); accA[0][3] = fmaf(x0, wA.w, accA[0][3]);
        accA[1][0] = fmaf(x1, wA.x, accA[1][0]); accA[1][1] = fmaf(x1, wA.y, accA[1][1]);
        accA[1][2] = fmaf(x1, wA.z, accA[1][2]); accA[1][3] = fmaf(x1, wA.w, accA[1][3]);
        accA[2][0] = fmaf(x2, wA.x, accA[2][0]); accA[2][1] = fmaf(x2, wA.y, accA[2][1]);
        accA[2][2] = fmaf(x2, wA.z, accA[2][2]); accA[2][3] = fmaf(x2, wA.w, accA[2][3]);
        accA[3][0] = fmaf(x3, wA.x, accA[3][0]); accA[3][1] = fmaf(x3, wA.y, accA[3][1]);
        accA[3][2] = fmaf(x3, wA.z, accA[3][2]); accA[3][3] = fmaf(x3, wA.w, accA[3][3]);
        accB[0][0] = fmaf(x0, wB.x, accB[0][0]); accB[0][1] = fmaf(x0, wB.y, accB[0][1]);
        accB[0][2] = fmaf(x0, wB.z, accB[0][2]); accB[0][3] = fmaf(x0, wB.w, accB[0][3]);
        accB[1][0] = fmaf(x1, wB.x, accB[1][0]); accB[1][1] = fmaf(x1, wB.y, accB[1][1]);
        accB[1][2] = fmaf(x1, wB.z, accB[1][2]); accB[1][3] = fmaf(x1, wB.w, accB[1][3]);
        accB[2][0] = fmaf(x2, wB.x, accB[2][0]); accB[2][1] = fmaf(x2, wB.y, accB[2][1]);
        accB[2][2] = fmaf(x2, wB.z, accB[2][2]); accB[2][3] = fmaf(x2, wB.w, accB[2][3]);
        accB[3][0] = fmaf(x3, wB.x, accB[3][0]); accB[3][1] = fmaf(x3, wB.y, accB[3][1]);
        accB[3][2] = fmaf(x3, wB.z, accB[3][2]); accB[3][3] = fmaf(x3, wB.w, accB[3][3]);
    }
#pragma unroll
    for (int nn = 0; nn < 4; nn++) {
        size_t row = (size_t)(base + 4 * ng + nn) * 2 * D;
        float4 va = make_float4(accA[nn][0], accA[nn][1], accA[nn][2], accA[nn][3]);
        float4 vb = make_float4(accB[nn][0], accB[nn][1], accB[nn][2], accB[nn][3]);
        *(reinterpret_cast<float4*>(g_ab + row) + cg) = va;
        *(reinterpret_cast<float4*>(g_ab + row + D) + cg) = vb;
    }
}

// ---------------- edge kernel: 4 edges/warp in flight ----------------
__global__ void __launch_bounds__(256) k_edge(const int* __restrict__ src,
                                              const int* __restrict__ dst,
                                              const float* __restrict__ bl,
                                              const float* __restrict__ Wf,
                                              const float* __restrict__ bf,
                                              float* __restrict__ out) {
    int lane = threadIdx.x & 31;
    int gw = (blockIdx.x * blockDim.x + threadIdx.x) >> 5;
    int nw = (gridDim.x * blockDim.x) >> 5;

    float bf0 = bf[0], bf1 = bf[1];
    float wf0[4], wf1[4];
    float4 bl4 = *(reinterpret_cast<const float4*>(bl) + lane);
#pragma unroll
    for (int i = 0; i < 4; i++) {
        wf0[i] = Wf[(4 * lane + i) * 2 + 0];
        wf1[i] = Wf[(4 * lane + i) * 2 + 1];
    }

    for (int e0 = gw * 4; e0 < N_EDGES; e0 += nw * 4) {
        float4 a[4], c[4];
#pragma unroll
        for (int ee = 0; ee < 4; ee++) {
            int s = src[e0 + ee];
            int d = dst[e0 + ee];
            a[ee] = __ldg(reinterpret_cast<const float4*>(g_ab + (size_t)s * 2 * D) + lane);
            c[ee] = __ldg(reinterpret_cast<const float4*>(g_ab + (size_t)d * 2 * D + D) + lane);
        }
        float z0[4], z1[4];
#pragma unroll
        for (int ee = 0; ee < 4; ee++) {
            float h0 = fmaxf(a[ee].x + c[ee].x + bl4.x, 0.f);
            float h1 = fmaxf(a[ee].y + c[ee].y + bl4.y, 0.f);
            float h2v = fmaxf(a[ee].z + c[ee].z + bl4.z, 0.f);
            float h3 = fmaxf(a[ee].w + c[ee].w + bl4.w, 0.f);
            z0[ee] = fmaf(h0, wf0[0], fmaf(h1, wf0[1], fmaf(h2v, wf0[2], h3 * wf0[3])));
            z1[ee] = fmaf(h0, wf1[0], fmaf(h1, wf1[1], fmaf(h2v, wf1[2], h3 * wf1[3])));
        }
#pragma unroll
        for (int off = 16; off; off >>= 1) {
#pragma unroll
            for (int ee = 0; ee < 4; ee++) {
                z0[ee] += __shfl_xor_sync(0xffffffffu, z0[ee], off);
                z1[ee] += __shfl_xor_sync(0xffffffffu, z1[ee], off);
            }
        }
        if (lane == 0) {
#pragma unroll
            for (int ee = 0; ee < 4; ee++) {
                float x0 = z0[ee] + bf0, x1 = z1[ee] + bf1;
                float m = fmaxf(x0, x1);
                float lse = m + logf(expf(x0 - m) + expf(x1 - m));
                *reinterpret_cast<float2*>(out + (size_t)(e0 + ee) * 2) =
                    make_float2(x0 - lse, x1 - lse);
            }
        }
    }
}

// ---------------- launch ----------------
extern "C" void kernel_launch(void* const* d_in, const int* in_sizes, int n_in,
                              void* d_out, int out_size) {
    const float* x     = (const float*)d_in[0];
    const int*   eidx  = (const int*)d_in[1];
    const float* W1    = (const float*)d_in[2];
    const float* b1    = (const float*)d_in[3];
    const float* W2    = (const float*)d_in[4];
    const float* b2    = (const float*)d_in[5];
    const float* Wlin1 = (const float*)d_in[6];
    const float* blin1 = (const float*)d_in[7];
    const float* Wfin  = (const float*)d_in[8];
    const float* bfin  = (const float*)d_in[9];
    float* out = (float*)d_out;

    const int* src = eidx;
    const int* dst = eidx + N_EDGES;

    static float *p_h = nullptr, *p_hb = nullptr, *p_h2 = nullptr;
    if (!p_h)  cudaGetSymbolAddress((void**)&p_h,  g_h);
    if (!p_hb) cudaGetSymbolAddress((void**)&p_hb, g_hb);
    if (!p_h2) cudaGetSymbolAddress((void**)&p_h2, g_h2);

    const int ND = N_NODES * D;
    const int EB = (N_EDGES + 255) / 256;

    // CSR build (shared by both GCN layers)
    k_zero_deg<<<(N_NODES + 255) / 256, 256>>>();
    k_deg<<<EB, 256>>>(dst);
    k_scan<<<1, 1024>>>();
    k_scatter<<<EB, 256>>>(src, dst);

    // layer 1: h = relu(GCN(x@W1))
    k_mm1<<<(ND + 255) / 256, 256>>>(x, W1);
    k_gcn<<<(N_NODES + 7) / 8, 256>>>(p_h, p_hb, b1);

    // layer 2: h2 = relu(GCN(hb@W2))
    k_mm128<<<N_PAD / 32, 256>>>(p_hb, W2, p_h);
    k_gcn<<<(N_NODES + 7) / 8, 256>>>(p_h, p_h2, b2);

    // edge MLP factorization
    k_ab<<<N_PAD / 32, 256>>>(p_h2, Wlin1);

    // per-edge epilogue
    k_edge<<<2368, 256>>>(src, dst, blin1, Wfin, bfin, out);
}

// round 6
// speedup vs baseline: 5.1664x; 1.1284x over previous
#include <cuda_runtime.h>
#include <cuda_fp16.h>
#include <math.h>

#define N_NODES 50000
#define N_PAD   50048            // multiple of 32 for GEMM tiling; pad rows stay 0
#define N_EDGES 800000
#define D 128

// ---------------- scratch (__device__ globals; no allocations) ----------------
__device__ int    g_deg[N_NODES];
__device__ int    g_ptr[N_NODES + 1];
__device__ int    g_cnt[N_NODES];
__device__ int    g_es[N_EDGES];           // src id per dst-sorted slot
__device__ float  g_dinv[N_NODES];
__device__ float  g_h[N_PAD * D];          // ping
__device__ float  g_hb[N_PAD * D];         // pong
__device__ float  g_h2[N_PAD * D];         // layer-2 output features
__device__ __half g_abh[N_PAD * 2 * D];    // [A | B] per node, fp16

// ---------------- f32x2 packed-FMA helpers ----------------
__device__ __forceinline__ unsigned long long pk2(float lo, float hi) {
    unsigned long long r;
    asm("mov.b64 %0, {%1, %2};" : "=l"(r) : "f"(lo), "f"(hi));
    return r;
}
__device__ __forceinline__ unsigned long long ffma2(unsigned long long a,
                                                    unsigned long long b,
                                                    unsigned long long c) {
    unsigned long long d;
    asm("fma.rn.f32x2 %0, %1, %2, %3;" : "=l"(d) : "l"(a), "l"(b), "l"(c));
    return d;
}
__device__ __forceinline__ float2 upk2(unsigned long long v) {
    float2 f;
    asm("mov.b64 {%0, %1}, %2;" : "=f"(f.x), "=f"(f.y) : "l"(v));
    return f;
}

// ---------------- fused: zero deg + h = x @ W1 (D_IN=8) ----------------
__global__ void k_mm1z(const float* __restrict__ x, const float* __restrict__ W1) {
    int idx = blockIdx.x * blockDim.x + threadIdx.x;
    if (idx < N_NODES) g_deg[idx] = 0;
    if (idx >= N_NODES * D) return;
    int node = idx >> 7;
    int j = idx & 127;
    float acc = 0.0f;
#pragma unroll
    for (int k = 0; k < 8; k++)
        acc = fmaf(x[node * 8 + k], W1[k * D + j], acc);
    g_h[idx] = acc;
}

__global__ void k_deg(const int* __restrict__ dst) {
    int e = blockIdx.x * blockDim.x + threadIdx.x;
    if (e < N_EDGES) atomicAdd(&g_deg[dst[e]], 1);
}

// single-block exclusive scan over degrees; also dinv + cnt init
__global__ void k_scan(void) {
    __shared__ int part[1024];
    int t = threadIdx.x;
    const int CH = (N_NODES + 1023) / 1024;
    int begin = t * CH;
    int end = begin + CH; if (end > N_NODES) end = N_NODES;
    int s = 0;
    for (int i = begin; i < end; i++) s += g_deg[i];
    part[t] = s;
    __syncthreads();
    for (int off = 1; off < 1024; off <<= 1) {
        int v = (t >= off) ? part[t - off] : 0;
        __syncthreads();
        part[t] += v;
        __syncthreads();
    }
    int run = (t == 0) ? 0 : part[t - 1];
    for (int i = begin; i < end; i++) {
        int d = g_deg[i];
        g_ptr[i] = run;
        g_cnt[i] = run;
        g_dinv[i] = rsqrtf((float)d + 1.0f);
        run += d;
    }
    if (t == 1023) g_ptr[N_NODES] = run;
}

__global__ void k_scatter(const int* __restrict__ src, const int* __restrict__ dst) {
    int e = blockIdx.x * blockDim.x + threadIdx.x;
    if (e < N_EDGES) {
        int d = dst[e];
        int pos = atomicAdd(&g_cnt[d], 1);
        g_es[pos] = src[e];
    }
}

// ---------------- fused GCN agg (CSR, warp/node, x4 unrolled) + self + bias + relu ----------------
__global__ void __launch_bounds__(256) k_gcn(const float* __restrict__ hin,
                                             float* __restrict__ hout,
                                             const float* __restrict__ b) {
    int warp = threadIdx.x >> 5;
    int lane = threadIdx.x & 31;
    int node = blockIdx.x * 8 + warp;
    if (node >= N_NODES) return;

    int p0 = g_ptr[node], p1 = g_ptr[node + 1];
    float4 acc = make_float4(0.f, 0.f, 0.f, 0.f);
    int i = p0;
    for (; i + 4 <= p1; i += 4) {
        int s0 = g_es[i], s1 = g_es[i + 1], s2 = g_es[i + 2], s3 = g_es[i + 3];
        float w0 = g_dinv[s0], w1 = g_dinv[s1], w2 = g_dinv[s2], w3 = g_dinv[s3];
        float4 v0 = __ldg(reinterpret_cast<const float4*>(hin + (size_t)s0 * D) + lane);
        float4 v1 = __ldg(reinterpret_cast<const float4*>(hin + (size_t)s1 * D) + lane);
        float4 v2 = __ldg(reinterpret_cast<const float4*>(hin + (size_t)s2 * D) + lane);
        float4 v3 = __ldg(reinterpret_cast<const float4*>(hin + (size_t)s3 * D) + lane);
        acc.x = fmaf(v0.x, w0, fmaf(v1.x, w1, fmaf(v2.x, w2, fmaf(v3.x, w3, acc.x))));
        acc.y = fmaf(v0.y, w0, fmaf(v1.y, w1, fmaf(v2.y, w2, fmaf(v3.y, w3, acc.y))));
        acc.z = fmaf(v0.z, w0, fmaf(v1.z, w1, fmaf(v2.z, w2, fmaf(v3.z, w3, acc.z))));
        acc.w = fmaf(v0.w, w0, fmaf(v1.w, w1, fmaf(v2.w, w2, fmaf(v3.w, w3, acc.w))));
    }
    for (; i < p1; i++) {
        int s = g_es[i];
        float w = g_dinv[s];
        float4 v = __ldg(reinterpret_cast<const float4*>(hin + (size_t)s * D) + lane);
        acc.x = fmaf(v.x, w, acc.x);
        acc.y = fmaf(v.y, w, acc.y);
        acc.z = fmaf(v.z, w, acc.z);
        acc.w = fmaf(v.w, w, acc.w);
    }
    float di = g_dinv[node];
    float di2 = di * di;
    float4 self = *(reinterpret_cast<const float4*>(hin + (size_t)node * D) + lane);
    float4 bb = *(reinterpret_cast<const float4*>(b) + lane);
    float4 r;
    r.x = fmaxf(fmaf(acc.x, di, fmaf(self.x, di2, bb.x)), 0.f);
    r.y = fmaxf(fmaf(acc.y, di, fmaf(self.y, di2, bb.y)), 0.f);
    r.z = fmaxf(fmaf(acc.z, di, fmaf(self.z, di2, bb.z)), 0.f);
    r.w = fmaxf(fmaf(acc.w, di, fmaf(self.w, di2, bb.w)), 0.f);
    *(reinterpret_cast<float4*>(hout + (size_t)node * D) + lane) = r;
}

// ---------------- out = in @ W (128x128): 32-node tile, f32x2 packed FMA ----------------
__global__ void __launch_bounds__(256) k_mm128(const float* __restrict__ in,
                                               const float* __restrict__ W,
                                               float* __restrict__ out) {
    __shared__ float sx[32][D];
    int base = blockIdx.x * 32;
    const float4* in4 = reinterpret_cast<const float4*>(in + (size_t)base * D);
    float4* sx4 = reinterpret_cast<float4*>(&sx[0][0]);
#pragma unroll
    for (int i = threadIdx.x; i < 32 * D / 4; i += 256) sx4[i] = in4[i];
    __syncthreads();

    int cg = threadIdx.x & 31;   // 4-col group
    int ng = threadIdx.x >> 5;   // 4-node group
    unsigned long long acc[4][2] = {};
#pragma unroll 4
    for (int k = 0; k < D; k++) {
        float4 w = __ldg(reinterpret_cast<const float4*>(W + k * D) + cg);
        unsigned long long w01 = pk2(w.x, w.y);
        unsigned long long w23 = pk2(w.z, w.w);
#pragma unroll
        for (int nn = 0; nn < 4; nn++) {
            float x = sx[4 * ng + nn][k];
            unsigned long long xb = pk2(x, x);
            acc[nn][0] = ffma2(xb, w01, acc[nn][0]);
            acc[nn][1] = ffma2(xb, w23, acc[nn][1]);
        }
    }
#pragma unroll
    for (int nn = 0; nn < 4; nn++) {
        float2 lo = upk2(acc[nn][0]);
        float2 hi = upk2(acc[nn][1]);
        float4 v = make_float4(lo.x, lo.y, hi.x, hi.y);
        *(reinterpret_cast<float4*>(out + (size_t)(base + 4 * ng + nn) * D) + cg) = v;
    }
}

// ---------------- g_abh = fp16( h2 @ [Wl_top | Wl_bot] ): 32-node tile, f32x2 ----------------
__global__ void __launch_bounds__(256) k_ab(const float* __restrict__ h2,
                                            const float* __restrict__ Wl) {
    __shared__ float sx[32][D];
    int base = blockIdx.x * 32;
    const float4* in4 = reinterpret_cast<const float4*>(h2 + (size_t)base * D);
    float4* sx4 = reinterpret_cast<float4*>(&sx[0][0]);
#pragma unroll
    for (int i = threadIdx.x; i < 32 * D / 4; i += 256) sx4[i] = in4[i];
    __syncthreads();

    int cg = threadIdx.x & 31;
    int ng = threadIdx.x >> 5;
    unsigned long long accA[4][2] = {};
    unsigned long long accB[4][2] = {};
#pragma unroll 2
    for (int k = 0; k < D; k++) {
        float4 wA = __ldg(reinterpret_cast<const float4*>(Wl + k * D) + cg);
        float4 wB = __ldg(reinterpret_cast<const float4*>(Wl + (D + k) * D) + cg);
        unsigned long long wa01 = pk2(wA.x, wA.y);
        unsigned long long wa23 = pk2(wA.z, wA.w);
        unsigned long long wb01 = pk2(wB.x, wB.y);
        unsigned long long wb23 = pk2(wB.z, wB.w);
#pragma unroll
        for (int nn = 0; nn < 4; nn++) {
            float x = sx[4 * ng + nn][k];
            unsigned long long xb = pk2(x, x);
            accA[nn][0] = ffma2(xb, wa01, accA[nn][0]);
            accA[nn][1] = ffma2(xb, wa23, accA[nn][1]);
            accB[nn][0] = ffma2(xb, wb01, accB[nn][0]);
            accB[nn][1] = ffma2(xb, wb23, accB[nn][1]);
        }
    }
#pragma unroll
    for (int nn = 0; nn < 4; nn++) {
        size_t row = (size_t)(base + 4 * ng + nn) * 2 * D;
        float2 a0 = upk2(accA[nn][0]);
        float2 a1 = upk2(accA[nn][1]);
        float2 b0 = upk2(accB[nn][0]);
        float2 b1 = upk2(accB[nn][1]);
        __half2 ha0 = __floats2half2_rn(a0.x, a0.y);
        __half2 ha1 = __floats2half2_rn(a1.x, a1.y);
        __half2 hb0 = __floats2half2_rn(b0.x, b0.y);
        __half2 hb1 = __floats2half2_rn(b1.x, b1.y);
        uint2 ua, ub;
        ua.x = *reinterpret_cast<unsigned*>(&ha0);
        ua.y = *reinterpret_cast<unsigned*>(&ha1);
        ub.x = *reinterpret_cast<unsigned*>(&hb0);
        ub.y = *reinterpret_cast<unsigned*>(&hb1);
        *reinterpret_cast<uint2*>(&g_abh[row + 4 * cg]) = ua;
        *reinterpret_cast<uint2*>(&g_abh[row + D + 4 * cg]) = ub;
    }
}

// ---------------- edge kernel: 8 edges/warp in flight, fp16 gathers ----------------
#define EPW 8
__global__ void __launch_bounds__(256) k_edge(const int* __restrict__ src,
                                              const int* __restrict__ dst,
                                              const float* __restrict__ bl,
                                              const float* __restrict__ Wf,
                                              const float* __restrict__ bf,
                                              float* __restrict__ out) {
    int lane = threadIdx.x & 31;
    int gw = (blockIdx.x * blockDim.x + threadIdx.x) >> 5;
    int nw = (gridDim.x * blockDim.x) >> 5;

    float bf0 = bf[0], bf1 = bf[1];
    float wf0[4], wf1[4];
    float4 bl4 = *(reinterpret_cast<const float4*>(bl) + lane);
#pragma unroll
    for (int i = 0; i < 4; i++) {
        wf0[i] = Wf[(4 * lane + i) * 2 + 0];
        wf1[i] = Wf[(4 * lane + i) * 2 + 1];
    }

    for (int e0 = gw * EPW; e0 < N_EDGES; e0 += nw * EPW) {
        uint2 ua[EPW], ub[EPW];
#pragma unroll
        for (int ee = 0; ee < EPW; ee++) {
            int s = src[e0 + ee];
            int d = dst[e0 + ee];
            ua[ee] = __ldg(reinterpret_cast<const uint2*>(g_abh + (size_t)s * 2 * D) + lane);
            ub[ee] = __ldg(reinterpret_cast<const uint2*>(g_abh + (size_t)d * 2 * D + D) + lane);
        }
        float z0[EPW], z1[EPW];
#pragma unroll
        for (int ee = 0; ee < EPW; ee++) {
            float2 a0 = __half22float2(*reinterpret_cast<__half2*>(&ua[ee].x));
            float2 a1 = __half22float2(*reinterpret_cast<__half2*>(&ua[ee].y));
            float2 b0 = __half22float2(*reinterpret_cast<__half2*>(&ub[ee].x));
            float2 b1 = __half22float2(*reinterpret_cast<__half2*>(&ub[ee].y));
            float h0 = fmaxf(a0.x + b0.x + bl4.x, 0.f);
            float h1 = fmaxf(a0.y + b0.y + bl4.y, 0.f);
            float h2v = fmaxf(a1.x + b1.x + bl4.z, 0.f);
            float h3 = fmaxf(a1.y + b1.y + bl4.w, 0.f);
            z0[ee] = fmaf(h0, wf0[0], fmaf(h1, wf0[1], fmaf(h2v, wf0[2], h3 * wf0[3])));
            z1[ee] = fmaf(h0, wf1[0], fmaf(h1, wf1[1], fmaf(h2v, wf1[2], h3 * wf1[3])));
        }
#pragma unroll
        for (int off = 16; off; off >>= 1) {
#pragma unroll
            for (int ee = 0; ee < EPW; ee++) {
                z0[ee] += __shfl_xor_sync(0xffffffffu, z0[ee], off);
                z1[ee] += __shfl_xor_sync(0xffffffffu, z1[ee], off);
            }
        }
        // distribute: lane ee finalizes edge ee (parallel log-softmax, coalesced store)
        float x0 = 0.f, x1 = 0.f;
#pragma unroll
        for (int ee = 0; ee < EPW; ee++) {
            if (lane == ee) { x0 = z0[ee]; x1 = z1[ee]; }
        }
        if (lane < EPW) {
            x0 += bf0;
            x1 += bf1;
            float m = fmaxf(x0, x1);
            float lse = m + __logf(__expf(x0 - m) + __expf(x1 - m));
            *reinterpret_cast<float2*>(out + (size_t)(e0 + lane) * 2) =
                make_float2(x0 - lse, x1 - lse);
        }
    }
}

// ---------------- launch ----------------
extern "C" void kernel_launch(void* const* d_in, const int* in_sizes, int n_in,
                              void* d_out, int out_size) {
    const float* x     = (const float*)d_in[0];
    const int*   eidx  = (const int*)d_in[1];
    const float* W1    = (const float*)d_in[2];
    const float* b1    = (const float*)d_in[3];
    const float* W2    = (const float*)d_in[4];
    const float* b2    = (const float*)d_in[5];
    const float* Wlin1 = (const float*)d_in[6];
    const float* blin1 = (const float*)d_in[7];
    const float* Wfin  = (const float*)d_in[8];
    const float* bfin  = (const float*)d_in[9];
    float* out = (float*)d_out;

    const int* src = eidx;
    const int* dst = eidx + N_EDGES;

    static float *p_h = nullptr, *p_hb = nullptr, *p_h2 = nullptr;
    if (!p_h)  cudaGetSymbolAddress((void**)&p_h,  g_h);
    if (!p_hb) cudaGetSymbolAddress((void**)&p_hb, g_hb);
    if (!p_h2) cudaGetSymbolAddress((void**)&p_h2, g_h2);

    const int ND = N_NODES * D;
    const int EB = (N_EDGES + 255) / 256;

    // CSR build + layer-1 projection (zero_deg fused into mm1)
    k_mm1z<<<(ND + 255) / 256, 256>>>(x, W1);
    k_deg<<<EB, 256>>>(dst);
    k_scan<<<1, 1024>>>();
    k_scatter<<<EB, 256>>>(src, dst);

    // layer 1: h = relu(GCN(x@W1))
    k_gcn<<<(N_NODES + 7) / 8, 256>>>(p_h, p_hb, b1);

    // layer 2: h2 = relu(GCN(hb@W2))
    k_mm128<<<N_PAD / 32, 256>>>(p_hb, W2, p_h);
    k_gcn<<<(N_NODES + 7) / 8, 256>>>(p_h, p_h2, b2);

    // edge MLP factorization (fp16 output)
    k_ab<<<N_PAD / 32, 256>>>(p_h2, Wlin1);

    // per-edge epilogue
    k_edge<<<2368, 256>>>(src, dst, blin1, Wfin, bfin, out);
}